// round 5
// baseline (speedup 1.0000x reference)
#include <cuda_runtime.h>
#include <math.h>

#define D    1024
#define H    8
#define HD   128
#define T    8193
#define NB3  129                      // token-sweep blocks (64 tokens each)
#define SCALE 0.08838834764831845f    // 1/sqrt(128)

// ---- scratch (device globals; no allocation allowed) ----
__device__ float g_u[H * D];          // u_h = Wk_h^T q0_h
__device__ float g_p[H * T];          // exp(score) (unnormalized probs)
__device__ float g_S[H];              // per-head sum of exp
__device__ float g_w[H * D];          // unnormalized weighted token sums
__device__ float g_attn0[D];
__device__ float g_out0[D];
__device__ unsigned int g_cnt;

// ===========================================================================
// kA: fused q0 + u, plus scratch zeroing.
//   64 blocks: b -> (h = b>>3, jc = b&7). Each block computes q0 for its head
//   (redundant x8, L2-served) then u[h][jc*128 .. jc*128+127].
// ===========================================================================
__global__ void kA_prep(const float* __restrict__ Wq,
                        const float* __restrict__ bq,
                        const float* __restrict__ Wk,
                        const float* __restrict__ cls) {
    __shared__ float q0s[HD];
    __shared__ float part[256];
    int tid = threadIdx.x, warp = tid >> 5, lane = tid & 31;
    int b = blockIdx.x, h = b >> 3, jc = b & 7;

    // zero scratch (done by subset of blocks; all kA blocks precede kB)
    if (b < 32) g_w[b * 256 + tid] = 0.f;
    if (b == 32) {
        if (tid < H) g_S[tid] = 0.f;
        if (tid == 8) g_cnt = 0u;
    }

    // q0 for this head: 8 warps x 16 rows
    const float4* cls4 = reinterpret_cast<const float4*>(cls);
    #pragma unroll
    for (int rr = 0; rr < 16; rr++) {
        int row = h * HD + warp * 16 + rr;
        const float4* wrow = reinterpret_cast<const float4*>(Wq) + (size_t)row * (D / 4);
        float acc = 0.f;
        #pragma unroll
        for (int k = lane; k < D / 4; k += 32) {
            float4 a = wrow[k], c = cls4[k];
            acc += a.x * c.x + a.y * c.y + a.z * c.z + a.w * c.w;
        }
        #pragma unroll
        for (int o = 16; o; o >>= 1) acc += __shfl_xor_sync(0xffffffffu, acc, o);
        if (lane == 0) q0s[warp * 16 + rr] = acc + bq[row];
    }
    __syncthreads();

    // u[h][j] for j in [jc*128, jc*128+128): two threads split the d-range
    int j  = jc * HD + (tid & 127);
    int dh = tid >> 7;                 // 0 or 1
    float acc = 0.f;
    #pragma unroll 8
    for (int d = dh * 64; d < dh * 64 + 64; d++)
        acc += q0s[d] * Wk[(size_t)(h * HD + d) * D + j];
    part[tid] = acc;
    __syncthreads();
    if (tid < 128)
        g_u[h * D + jc * HD + tid] = part[tid] + part[tid + 128];
}

// ===========================================================================
// kB: single sweep over tokens. scores -> exp (one-pass, no max) ->
//     per-head sum atomics + weighted token sums atomics into g_w.
// ===========================================================================
__global__ void kB_sweep(const float* __restrict__ x, const float* __restrict__ cls) {
    __shared__ float us[H * D];        // 32 KB
    __shared__ float wt[64 * 8];       // exp weights [tt][h]
    int tid = threadIdx.x;
    for (int i = tid; i < H * D; i += 256) us[i] = g_u[i];
    __syncthreads();

    int warp = tid >> 5, lane = tid & 31;
    int base  = blockIdx.x * 64;
    int tbase = base + warp * 8;

    // ---- scores for 8 tokens x 8 heads per warp ----
    const float* ptr[8];
    #pragma unroll
    for (int tt = 0; tt < 8; tt++) {
        int s = tbase + tt;
        ptr[tt] = (s <= 0 || s >= T) ? cls : x + (size_t)(s - 1) * D;
    }
    float acc[64];
    #pragma unroll
    for (int i = 0; i < 64; i++) acc[i] = 0.f;
    for (int k = 0; k < 32; k++) {
        int j = k * 32 + lane;
        float uv[8];
        #pragma unroll
        for (int h = 0; h < 8; h++) uv[h] = us[h * D + j];
        #pragma unroll
        for (int tt = 0; tt < 8; tt++) {
            float xv = ptr[tt][j];
            #pragma unroll
            for (int h = 0; h < 8; h++) acc[tt * 8 + h] += xv * uv[h];
        }
    }
    #pragma unroll
    for (int o = 16; o; o >>= 1) {
        #pragma unroll
        for (int i = 0; i < 64; i++) acc[i] += __shfl_xor_sync(0xffffffffu, acc[i], o);
    }
    // exp + store (lane r and r+32 own entries r, r+32 of this warp's 64)
    #pragma unroll
    for (int rr = 0; rr < 2; rr++) {
        int r = lane + rr * 32;
        int tt = r >> 3, h = r & 7;
        int s = tbase + tt;
        int slot = (warp * 8 + tt) * 8 + h;
        if (s < T) {
            float e = expf(acc[r] * SCALE);
            wt[slot] = e;
            g_p[h * T + s] = e;
        } else {
            wt[slot] = 0.f;
        }
    }
    __syncthreads();

    // ---- per-head block sum -> atomic S (one warp per head) ----
    {
        int h = warp;
        float ssum = 0.f;
        for (int t = lane; t < 64; t += 32) ssum += wt[t * 8 + h];
        #pragma unroll
        for (int o = 16; o; o >>= 1) ssum += __shfl_xor_sync(0xffffffffu, ssum, o);
        if (lane == 0) atomicAdd(&g_S[h], ssum);
    }

    // ---- weighted token sums (thread owns dims [4*tid, 4*tid+4)) ----
    float a[8][4];
    #pragma unroll
    for (int h = 0; h < 8; h++) { a[h][0] = a[h][1] = a[h][2] = a[h][3] = 0.f; }
    for (int tt = 0; tt < 64; tt++) {
        int s = base + tt;
        if (s >= T) break;
        const float* p = (s == 0) ? cls : x + (size_t)(s - 1) * D;
        float4 xv = reinterpret_cast<const float4*>(p)[tid];
        #pragma unroll
        for (int h = 0; h < 8; h++) {
            float w = wt[tt * 8 + h];
            a[h][0] += w * xv.x; a[h][1] += w * xv.y;
            a[h][2] += w * xv.z; a[h][3] += w * xv.w;
        }
    }
    #pragma unroll
    for (int h = 0; h < 8; h++) {
        float* dst = &g_w[h * D + tid * 4];
        atomicAdd(dst + 0, a[h][0]); atomicAdd(dst + 1, a[h][1]);
        atomicAdd(dst + 2, a[h][2]); atomicAdd(dst + 3, a[h][3]);
    }
}

// ===========================================================================
// kC: blocks [0,128): attn0[r] = (Wv[r,:] . w_h)/S_h + bv[r]  (warp per row)
//     blocks [128,161): A output: A[s] = (1/8) sum_h p[h,s]/S_h
// ===========================================================================
__global__ void kC_mid(const float* __restrict__ Wv, const float* __restrict__ bv,
                       float* __restrict__ out) {
    int b = blockIdx.x, tid = threadIdx.x;
    if (b < 128) {
        int warp = tid >> 5, lane = tid & 31;
        int row = b * 8 + warp;
        int h = row >> 7;
        const float4* row4 = reinterpret_cast<const float4*>(Wv) + (size_t)row * (D / 4);
        const float4* w4   = reinterpret_cast<const float4*>(&g_w[h * D]);
        float acc = 0.f;
        #pragma unroll
        for (int k = lane; k < D / 4; k += 32) {
            float4 a = row4[k], w = w4[k];
            acc += a.x * w.x + a.y * w.y + a.z * w.z + a.w * w.w;
        }
        #pragma unroll
        for (int o = 16; o; o >>= 1) acc += __shfl_xor_sync(0xffffffffu, acc, o);
        if (lane == 0) g_attn0[row] = acc / g_S[h] + bv[row];
    } else {
        __shared__ float rS[H];
        if (tid < H) rS[tid] = 1.f / g_S[tid];
        __syncthreads();
        int s = (b - 128) * 256 + tid;
        if (s >= 1 && s < T) {
            float a = 0.f;
            #pragma unroll
            for (int h = 0; h < 8; h++) a += g_p[h * T + s] * rS[h];
            out[7 + (s - 1)] = a * 0.125f;
        }
    }
}

// ===========================================================================
// kD: out0 = Wo . attn0 + bo  (warp per row), last-finishing block computes
//     logits/softmax/argmax and writes the scalar outputs.
// ===========================================================================
__global__ void kD_final(const float* __restrict__ Wo, const float* __restrict__ bo,
                         const float* __restrict__ Wc, const float* __restrict__ bc,
                         float* __restrict__ out) {
    __shared__ unsigned int s_last;
    __shared__ float lg[2];
    int tid = threadIdx.x, warp = tid >> 5, lane = tid & 31;
    int row = blockIdx.x * 8 + warp;

    {
        const float4* row4 = reinterpret_cast<const float4*>(Wo) + (size_t)row * (D / 4);
        const float4* a4   = reinterpret_cast<const float4*>(g_attn0);
        float acc = 0.f;
        #pragma unroll
        for (int k = lane; k < D / 4; k += 32) {
            float4 a = row4[k], v = a4[k];
            acc += a.x * v.x + a.y * v.y + a.z * v.z + a.w * v.w;
        }
        #pragma unroll
        for (int o = 16; o; o >>= 1) acc += __shfl_xor_sync(0xffffffffu, acc, o);
        if (lane == 0) g_out0[row] = acc + bo[row];
    }

    __threadfence();
    __syncthreads();
    if (tid == 0) s_last = atomicAdd(&g_cnt, 1u);
    __syncthreads();
    if (s_last != gridDim.x - 1) return;     // only the last-finishing block continues
    __threadfence();                          // acquire: see all g_out0 writes

    if (warp < 2) {
        const float4* row4 = reinterpret_cast<const float4*>(Wc) + (size_t)warp * (D / 4);
        const float4* o4   = reinterpret_cast<const float4*>(g_out0);
        float acc = 0.f;
        #pragma unroll
        for (int k = lane; k < D / 4; k += 32) {
            float4 a = row4[k], v = o4[k];
            acc += a.x * v.x + a.y * v.y + a.z * v.z + a.w * v.w;
        }
        #pragma unroll
        for (int o = 16; o; o >>= 1) acc += __shfl_xor_sync(0xffffffffu, acc, o);
        if (lane == 0) lg[warp] = acc + bc[warp];
    }
    __syncthreads();
    if (tid == 0) {
        float l0 = lg[0], l1 = lg[1];
        float mx = fmaxf(l0, l1);
        float e0 = expf(l0 - mx), e1 = expf(l1 - mx);
        float inv = 1.f / (e0 + e1);
        float p0 = e0 * inv, p1 = e1 * inv;
        float yhat = (p1 > p0) ? 1.f : 0.f;   // first-max tie-break like jnp.argmax
        out[0] = l0; out[1] = l1;             // top_instance
        out[2] = p0; out[3] = p1;             // Y_prob
        out[4] = yhat;                        // Y_hat
        out[5] = p0; out[6] = p1;             // y_probs
    }
}

extern "C" void kernel_launch(void* const* d_in, const int* in_sizes, int n_in,
                              void* d_out, int out_size) {
    const float* x   = (const float*)d_in[0];
    const float* cls = (const float*)d_in[1];
    const float* Wq  = (const float*)d_in[2];
    const float* bq  = (const float*)d_in[3];
    const float* Wk  = (const float*)d_in[4];
    // d_in[5] = bk: per-head constant shift of scores -> softmax-invariant, unused
    const float* Wv  = (const float*)d_in[6];
    const float* bv  = (const float*)d_in[7];
    const float* Wo  = (const float*)d_in[8];
    const float* bo  = (const float*)d_in[9];
    const float* Wc  = (const float*)d_in[10];
    const float* bc  = (const float*)d_in[11];
    float* out = (float*)d_out;

    kA_prep<<<64, 256>>>(Wq, bq, Wk, cls);
    kB_sweep<<<NB3, 256>>>(x, cls);
    kC_mid<<<161, 256>>>(Wv, bv, out);
    kD_final<<<128, 256>>>(Wo, bo, Wc, bc, out);
    (void)in_sizes; (void)n_in; (void)out_size;
}

// round 8
// speedup vs baseline: 1.3073x; 1.3073x over previous
#include <cuda_runtime.h>
#include <math.h>

#define D    1024
#define H    8
#define HD   128
#define T    8193
#define SCALE 0.08838834764831845f    // 1/sqrt(128)

// ---- scratch (device globals; no allocation allowed) ----
__device__ float g_q0[D];             // Wq@cls + bq
__device__ float g_u[H * D];          // u_h = Wk_h^T q0_h
__device__ float g_wcp[64 * 2 * D];   // Wc@Wo partials: [p][c][j]
__device__ float g_G[2 * H * D];      // G[c][h][j] = sum_d Wcmod[c,h*128+d]*Wv[h*128+d,j]
__device__ float g_bias[2];           // Wcmod.bv + Wc.bo + bc
__device__ float g_p[H * T];          // exp(score)
__device__ float g_S[H];              // per-head sum of exp
__device__ float g_w[H * D];          // unnormalized weighted token sums

// ===========================================================================
// K1 (192 blocks):
//   b in [0,128):  q0[b*8+warp] = Wq row . cls + bq      (warp per row)
//   b in [128,192): Wc@Wo partials over 16 Wo rows -> g_wcp
//   also zeroes g_G, g_w, g_S (before K2/K3 atomics; globals zero on 1st run)
// ===========================================================================
__global__ void K1(const float* __restrict__ Wq, const float* __restrict__ bq,
                   const float* __restrict__ Wo, const float* __restrict__ Wc,
                   const float* __restrict__ cls) {
    int tid = threadIdx.x, b = blockIdx.x;
    int gid = b * 256 + tid;

    // zero scratch used by later atomics
    if (gid < 2 * H * D)                 g_G[gid] = 0.f;
    else if (gid < 2 * H * D + H * D)    g_w[gid - 2 * H * D] = 0.f;
    else if (gid < 2 * H * D + H * D + H) g_S[gid - 2 * H * D - H * D] = 0.f;

    if (b < 128) {
        int warp = tid >> 5, lane = tid & 31;
        int row = b * 8 + warp;
        const float4* row4 = reinterpret_cast<const float4*>(Wq) + (size_t)row * (D / 4);
        const float4* c4   = reinterpret_cast<const float4*>(cls);
        float acc = 0.f;
        #pragma unroll
        for (int k = lane; k < D / 4; k += 32) {
            float4 a = row4[k], c = c4[k];
            acc += a.x * c.x + a.y * c.y + a.z * c.z + a.w * c.w;
        }
        #pragma unroll
        for (int o = 16; o; o >>= 1) acc += __shfl_xor_sync(0xffffffffu, acc, o);
        if (lane == 0) g_q0[row] = acc + bq[row];
    } else {
        int p = b - 128, r0 = p * 16;
        float a0x = 0.f, a0y = 0.f, a0z = 0.f, a0w = 0.f;
        float a1x = 0.f, a1y = 0.f, a1z = 0.f, a1w = 0.f;
        #pragma unroll
        for (int rr = 0; rr < 16; rr++) {
            int r = r0 + rr;
            float4 v = reinterpret_cast<const float4*>(Wo)[(size_t)r * (D / 4) + tid];
            float c0 = __ldg(&Wc[r]), c1 = __ldg(&Wc[D + r]);
            a0x += c0 * v.x; a0y += c0 * v.y; a0z += c0 * v.z; a0w += c0 * v.w;
            a1x += c1 * v.x; a1y += c1 * v.y; a1z += c1 * v.z; a1w += c1 * v.w;
        }
        reinterpret_cast<float4*>(&g_wcp[(p * 2 + 0) * D])[tid] = make_float4(a0x, a0y, a0z, a0w);
        reinterpret_cast<float4*>(&g_wcp[(p * 2 + 1) * D])[tid] = make_float4(a1x, a1y, a1z, a1w);
    }
}

// ===========================================================================
// K2 (130 blocks):
//   b in [0,64):    u chunk (h=b>>3, jc=b&7) from Wk + g_q0
//   b in [64,128):  G partials over 16 Wv rows (reduce Wcmod from g_wcp, atomic into g_G)
//   b == 128:       unused spare
//   b == 129:       bias: Wcmod.bv + Wc.bo + bc -> g_bias
// ===========================================================================
__global__ void K2(const float* __restrict__ Wk, const float* __restrict__ Wv,
                   const float* __restrict__ bv, const float* __restrict__ bo,
                   const float* __restrict__ bc, const float* __restrict__ Wc) {
    int tid = threadIdx.x, b = blockIdx.x;
    if (b < 64) {
        __shared__ float q0s[HD];
        __shared__ float part[256];
        int h = b >> 3, jc = b & 7;
        if (tid < 128) q0s[tid] = g_q0[h * HD + tid];
        __syncthreads();
        int j = jc * HD + (tid & 127);
        int dh = tid >> 7;
        float acc = 0.f;
        #pragma unroll 8
        for (int d = dh * 64; d < dh * 64 + 64; d++)
            acc += q0s[d] * Wk[(size_t)(h * HD + d) * D + j];
        part[tid] = acc;
        __syncthreads();
        if (tid < 128) g_u[h * D + jc * HD + tid] = part[tid] + part[tid + 128];
    } else if (b < 128) {
        __shared__ float wcm[2][16];
        int bg = b - 64, r0 = bg * 16, h = bg >> 3;
        if (tid < 32) {
            int c = tid >> 4, rr = tid & 15;
            float s = 0.f;
            #pragma unroll 8
            for (int p = 0; p < 64; p++) s += g_wcp[(p * 2 + c) * D + r0 + rr];
            wcm[c][rr] = s;
        }
        __syncthreads();
        float a0x = 0.f, a0y = 0.f, a0z = 0.f, a0w = 0.f;
        float a1x = 0.f, a1y = 0.f, a1z = 0.f, a1w = 0.f;
        #pragma unroll
        for (int rr = 0; rr < 16; rr++) {
            int r = r0 + rr;
            float4 v = reinterpret_cast<const float4*>(Wv)[(size_t)r * (D / 4) + tid];
            float c0 = wcm[0][rr], c1 = wcm[1][rr];
            a0x += c0 * v.x; a0y += c0 * v.y; a0z += c0 * v.z; a0w += c0 * v.w;
            a1x += c1 * v.x; a1y += c1 * v.y; a1z += c1 * v.z; a1w += c1 * v.w;
        }
        float* d0 = &g_G[(0 * H + h) * D + tid * 4];
        float* d1 = &g_G[(1 * H + h) * D + tid * 4];
        atomicAdd(d0 + 0, a0x); atomicAdd(d0 + 1, a0y); atomicAdd(d0 + 2, a0z); atomicAdd(d0 + 3, a0w);
        atomicAdd(d1 + 0, a1x); atomicAdd(d1 + 1, a1y); atomicAdd(d1 + 2, a1z); atomicAdd(d1 + 3, a1w);
    } else if (b == 129) {
        __shared__ float red0[256], red1[256];
        float4 m0 = make_float4(0.f, 0.f, 0.f, 0.f);
        float4 m1 = make_float4(0.f, 0.f, 0.f, 0.f);
        #pragma unroll 4
        for (int p = 0; p < 64; p++) {
            float4 v0 = reinterpret_cast<const float4*>(&g_wcp[(p * 2 + 0) * D])[tid];
            float4 v1 = reinterpret_cast<const float4*>(&g_wcp[(p * 2 + 1) * D])[tid];
            m0.x += v0.x; m0.y += v0.y; m0.z += v0.z; m0.w += v0.w;
            m1.x += v1.x; m1.y += v1.y; m1.z += v1.z; m1.w += v1.w;
        }
        float4 bvv = reinterpret_cast<const float4*>(bv)[tid];
        float4 bov = reinterpret_cast<const float4*>(bo)[tid];
        float4 wc0 = reinterpret_cast<const float4*>(Wc)[tid];
        float4 wc1 = reinterpret_cast<const float4*>(Wc)[256 + tid];
        float s0 = m0.x * bvv.x + m0.y * bvv.y + m0.z * bvv.z + m0.w * bvv.w
                 + wc0.x * bov.x + wc0.y * bov.y + wc0.z * bov.z + wc0.w * bov.w;
        float s1 = m1.x * bvv.x + m1.y * bvv.y + m1.z * bvv.z + m1.w * bvv.w
                 + wc1.x * bov.x + wc1.y * bov.y + wc1.z * bov.z + wc1.w * bov.w;
        red0[tid] = s0; red1[tid] = s1;
        __syncthreads();
        for (int o = 128; o; o >>= 1) {
            if (tid < o) { red0[tid] += red0[tid + o]; red1[tid] += red1[tid + o]; }
            __syncthreads();
        }
        if (tid == 0) { g_bias[0] = red0[0] + bc[0]; g_bias[1] = red1[0] + bc[1]; }
    }
}

// ===========================================================================
// K3 (129 blocks x 512 threads): one sweep over x.
//   scores (warp owns 4 tokens x 8 heads) -> exp -> g_p, atomic S,
//   weighted token sums -> atomic g_w.
// ===========================================================================
__global__ void __launch_bounds__(512) K3(const float* __restrict__ x,
                                          const float* __restrict__ cls) {
    __shared__ float us[H * D];        // 32 KB
    __shared__ float wt[64 * 8];       // exp weights [tt][h]
    int tid = threadIdx.x;
    #pragma unroll
    for (int i = 0; i < 16; i++) us[tid + i * 512] = g_u[tid + i * 512];
    __syncthreads();

    int warp = tid >> 5, lane = tid & 31;
    int base  = blockIdx.x * 64;
    int tbase = base + warp * 4;

    // ---- scores: 4 tokens x 8 heads per warp ----
    const float* ptr[4];
    #pragma unroll
    for (int tt = 0; tt < 4; tt++) {
        int s = tbase + tt;
        ptr[tt] = (s <= 0 || s >= T) ? cls : x + (size_t)(s - 1) * D;
    }
    float acc[32];
    #pragma unroll
    for (int i = 0; i < 32; i++) acc[i] = 0.f;
    for (int k = 0; k < 32; k++) {
        int j = k * 32 + lane;
        float uv[8];
        #pragma unroll
        for (int h = 0; h < 8; h++) uv[h] = us[h * D + j];
        #pragma unroll
        for (int tt = 0; tt < 4; tt++) {
            float xv = ptr[tt][j];
            #pragma unroll
            for (int h = 0; h < 8; h++) acc[tt * 8 + h] += xv * uv[h];
        }
    }
    #pragma unroll
    for (int o = 16; o; o >>= 1) {
        #pragma unroll
        for (int i = 0; i < 32; i++) acc[i] += __shfl_xor_sync(0xffffffffu, acc[i], o);
    }
    {
        int tt = lane >> 3, h = lane & 7;       // lane r owns acc[r]
        int s = tbase + tt;
        int slot = (warp * 4 + tt) * 8 + h;
        if (s < T) {
            float e = expf(acc[lane] * SCALE);
            wt[slot] = e;
            g_p[h * T + s] = e;
        } else {
            wt[slot] = 0.f;
        }
    }
    __syncthreads();

    // ---- per-head block sum -> atomic S (first 8 warps) ----
    if (warp < 8) {
        int h = warp;
        float ssum = 0.f;
        #pragma unroll
        for (int t = lane; t < 64; t += 32) ssum += wt[t * 8 + h];
        #pragma unroll
        for (int o = 16; o; o >>= 1) ssum += __shfl_xor_sync(0xffffffffu, ssum, o);
        if (lane == 0) atomicAdd(&g_S[h], ssum);
    }

    // ---- weighted token sums: thread owns dims [2*tid, 2*tid+2) ----
    float a[8][2];
    #pragma unroll
    for (int h = 0; h < 8; h++) { a[h][0] = 0.f; a[h][1] = 0.f; }
    for (int tt = 0; tt < 64; tt++) {
        int s = base + tt;
        if (s >= T) break;
        const float* p = (s == 0) ? cls : x + (size_t)(s - 1) * D;
        float2 xv = reinterpret_cast<const float2*>(p)[tid];
        #pragma unroll
        for (int h = 0; h < 8; h++) {
            float w = wt[tt * 8 + h];
            a[h][0] += w * xv.x; a[h][1] += w * xv.y;
        }
    }
    #pragma unroll
    for (int h = 0; h < 8; h++) {
        float* dst = &g_w[h * D + tid * 2];
        atomicAdd(dst + 0, a[h][0]); atomicAdd(dst + 1, a[h][1]);
    }
}

// ===========================================================================
// K4 (33 blocks):
//   b in [0,32): A[s] = (1/8) sum_h p[h,s]/S_h
//   b == 32:     logits_c = sum_h (G[c,h,:].w_h)/S_h + bias_c; softmax; outputs
// ===========================================================================
__global__ void K4(float* __restrict__ out) {
    __shared__ float rS[H];
    int tid = threadIdx.x, b = blockIdx.x;
    if (tid < H) rS[tid] = 1.f / g_S[tid];
    __syncthreads();

    if (b < 32) {
        int s = b * 256 + tid + 1;               // s in [1, 8193)
        float a = 0.f;
        #pragma unroll
        for (int h = 0; h < 8; h++) a += g_p[h * T + s] * rS[h];
        out[7 + (s - 1)] = a * 0.125f;
    } else {
        __shared__ float red0[256], red1[256];
        float l0 = 0.f, l1 = 0.f;
        #pragma unroll
        for (int h = 0; h < 8; h++) {
            float4 w4 = reinterpret_cast<const float4*>(&g_w[h * D])[tid];
            float4 g0 = reinterpret_cast<const float4*>(&g_G[(0 * H + h) * D])[tid];
            float4 g1 = reinterpret_cast<const float4*>(&g_G[(1 * H + h) * D])[tid];
            float r = rS[h];
            l0 += r * (g0.x * w4.x + g0.y * w4.y + g0.z * w4.z + g0.w * w4.w);
            l1 += r * (g1.x * w4.x + g1.y * w4.y + g1.z * w4.z + g1.w * w4.w);
        }
        red0[tid] = l0; red1[tid] = l1;
        __syncthreads();
        for (int o = 128; o; o >>= 1) {
            if (tid < o) { red0[tid] += red0[tid + o]; red1[tid] += red1[tid + o]; }
            __syncthreads();
        }
        if (tid == 0) {
            float L0 = red0[0] + g_bias[0], L1 = red1[0] + g_bias[1];
            float mx = fmaxf(L0, L1);
            float e0 = expf(L0 - mx), e1 = expf(L1 - mx);
            float inv = 1.f / (e0 + e1);
            float p0 = e0 * inv, p1 = e1 * inv;
            float yhat = (p1 > p0) ? 1.f : 0.f;
            out[0] = L0; out[1] = L1;            // top_instance
            out[2] = p0; out[3] = p1;            // Y_prob
            out[4] = yhat;                       // Y_hat
            out[5] = p0; out[6] = p1;            // y_probs
        }
    }
}

extern "C" void kernel_launch(void* const* d_in, const int* in_sizes, int n_in,
                              void* d_out, int out_size) {
    const float* x   = (const float*)d_in[0];
    const float* cls = (const float*)d_in[1];
    const float* Wq  = (const float*)d_in[2];
    const float* bq  = (const float*)d_in[3];
    const float* Wk  = (const float*)d_in[4];
    // d_in[5] = bk: per-head constant shift of scores -> softmax-invariant, unused
    const float* Wv  = (const float*)d_in[6];
    const float* bv  = (const float*)d_in[7];
    const float* Wo  = (const float*)d_in[8];
    const float* bo  = (const float*)d_in[9];
    const float* Wc  = (const float*)d_in[10];
    const float* bc  = (const float*)d_in[11];
    float* out = (float*)d_out;

    K1<<<192, 256>>>(Wq, bq, Wo, Wc, cls);
    K2<<<130, 256>>>(Wk, Wv, bv, bo, bc, Wc);
    K3<<<129, 512>>>(x, cls);
    K4<<<33, 256>>>(out);
    (void)in_sizes; (void)n_in; (void)out_size;
}

// round 9
// speedup vs baseline: 1.3765x; 1.0529x over previous
#include <cuda_runtime.h>
#include <math.h>

#define D    1024
#define H    8
#define HD   128
#define T    8193
#define NBLK 148
#define NTHR 512
#define SCALE 0.08838834764831845f    // 1/sqrt(128)

// ---- scratch (device globals; no allocation allowed) ----
__device__ float g_q0[D];             // Wq@cls + bq
__device__ float g_u[H * D];          // u_h = Wk_h^T q0_h
__device__ float g_wcp[64 * 2 * D];   // Wc@Wo partials: [p][c][j]
__device__ float g_G[2 * H * D];      // G[c][h][j]
__device__ float g_bias[2];
__device__ float g_S[H];              // per-head sum of exp
__device__ float g_w[H * D];          // unnormalized weighted token sums
__device__ unsigned int g_barcnt;     // grid barrier counter (self-resetting)
__device__ volatile unsigned int g_sense;  // ends each launch at 0 (even # barriers)

// Sense-reversing grid barrier. Safe: grid (148) <= #SMs -> all blocks resident.
__device__ __forceinline__ void grid_barrier(unsigned int ls) {
    __syncthreads();
    if (threadIdx.x == 0) {
        __threadfence();
        unsigned int old = atomicAdd(&g_barcnt, 1u);
        if (old == gridDim.x - 1) {
            g_barcnt = 0;              // all arrived; safe to reset
            __threadfence();
            g_sense = ls;
        } else {
            while (g_sense != ls) __nanosleep(32);
        }
        __threadfence();
    }
    __syncthreads();
}

union SmemU {
    float us[H * D];                               // phase C: 32 KB u vectors
    struct { float part[NTHR]; float q0s[HD]; float wcm[2][2][16]; } ab;
    struct { float red0[NTHR]; float red1[NTHR]; } d;
};

__global__ void __launch_bounds__(NTHR, 1)
Kfused(const float* __restrict__ x,  const float* __restrict__ cls,
       const float* __restrict__ Wq, const float* __restrict__ bq,
       const float* __restrict__ Wk, const float* __restrict__ Wv,
       const float* __restrict__ bv, const float* __restrict__ Wo,
       const float* __restrict__ bo, const float* __restrict__ Wc,
       const float* __restrict__ bc, float* __restrict__ out) {
    __shared__ SmemU su;
    __shared__ float s_wt[64 * 8];     // exp weights, persists C -> D
    __shared__ float s_rS[H];
    int tid = threadIdx.x, warp = tid >> 5, lane = tid & 31;
    int b = blockIdx.x;

    // ================= Phase A: q0 | Wc@Wo partials | zero scratch ==========
    if (b < 64) {
        // q0: 16 warps x 1 row each
        int row = b * 16 + warp;
        const float4* row4 = reinterpret_cast<const float4*>(Wq) + (size_t)row * (D / 4);
        const float4* c4   = reinterpret_cast<const float4*>(cls);
        float acc = 0.f;
        #pragma unroll
        for (int k = lane; k < D / 4; k += 32) {
            float4 a = row4[k], c = c4[k];
            acc += a.x * c.x + a.y * c.y + a.z * c.z + a.w * c.w;
        }
        #pragma unroll
        for (int o = 16; o; o >>= 1) acc += __shfl_xor_sync(0xffffffffu, acc, o);
        if (lane == 0) g_q0[row] = acc + bq[row];
    } else if (b < 96) {
        // Wc@Wo partials: two 256-thread halves, 16 Wo rows each
        int p = (b - 64) * 2 + (tid >> 8);
        int t2 = tid & 255;
        int r0 = p * 16;
        float a0x = 0.f, a0y = 0.f, a0z = 0.f, a0w = 0.f;
        float a1x = 0.f, a1y = 0.f, a1z = 0.f, a1w = 0.f;
        #pragma unroll
        for (int rr = 0; rr < 16; rr++) {
            int r = r0 + rr;
            float4 v = reinterpret_cast<const float4*>(Wo)[(size_t)r * (D / 4) + t2];
            float c0 = __ldg(&Wc[r]), c1 = __ldg(&Wc[D + r]);
            a0x += c0 * v.x; a0y += c0 * v.y; a0z += c0 * v.z; a0w += c0 * v.w;
            a1x += c1 * v.x; a1y += c1 * v.y; a1z += c1 * v.z; a1w += c1 * v.w;
        }
        reinterpret_cast<float4*>(&g_wcp[(p * 2 + 0) * D])[t2] = make_float4(a0x, a0y, a0z, a0w);
        reinterpret_cast<float4*>(&g_wcp[(p * 2 + 1) * D])[t2] = make_float4(a1x, a1y, a1z, a1w);
    } else if (b < 144) {
        int idx = (b - 96) * NTHR + tid;          // 0..24575
        if (idx < 2 * H * D) g_G[idx] = 0.f;
        else                 g_w[idx - 2 * H * D] = 0.f;
    } else if (b == 144) {
        if (tid < H) g_S[tid] = 0.f;
    }
    grid_barrier(1);

    // ================= Phase B: u | G | bias ================================
    if (b < 32) {
        // u: block covers head h = b>>2, two 128-col chunks (one per 256-thread half)
        int h = b >> 2;
        int half = tid >> 8, t2 = tid & 255;
        int jc = (b & 3) * 2 + half;
        if (tid < HD) su.ab.q0s[tid] = g_q0[h * HD + tid];
        __syncthreads();
        int j  = jc * HD + (t2 & 127);
        int dh = t2 >> 7;
        float acc = 0.f;
        #pragma unroll 8
        for (int d = dh * 64; d < dh * 64 + 64; d++)
            acc += su.ab.q0s[d] * Wk[(size_t)(h * HD + d) * D + j];
        su.ab.part[tid] = acc;
        __syncthreads();
        if (t2 < 128)
            g_u[h * D + jc * HD + t2] = su.ab.part[half * 256 + t2] + su.ab.part[half * 256 + t2 + 128];
    } else if (b < 64) {
        // G partials: two halves, 16 Wv rows each, atomic into g_G
        int half = tid >> 8, t2 = tid & 255;
        int bg = (b - 32) * 2 + half;
        int r0 = bg * 16, h = bg >> 3;
        if (t2 < 32) {
            int c = t2 >> 4, rr = t2 & 15;
            float s = 0.f;
            #pragma unroll 8
            for (int p = 0; p < 64; p++) s += g_wcp[(p * 2 + c) * D + r0 + rr];
            su.ab.wcm[half][c][rr] = s;
        }
        __syncthreads();
        float a0x = 0.f, a0y = 0.f, a0z = 0.f, a0w = 0.f;
        float a1x = 0.f, a1y = 0.f, a1z = 0.f, a1w = 0.f;
        #pragma unroll
        for (int rr = 0; rr < 16; rr++) {
            int r = r0 + rr;
            float4 v = reinterpret_cast<const float4*>(Wv)[(size_t)r * (D / 4) + t2];
            float c0 = su.ab.wcm[half][0][rr], c1 = su.ab.wcm[half][1][rr];
            a0x += c0 * v.x; a0y += c0 * v.y; a0z += c0 * v.z; a0w += c0 * v.w;
            a1x += c1 * v.x; a1y += c1 * v.y; a1z += c1 * v.z; a1w += c1 * v.w;
        }
        float* d0 = &g_G[(0 * H + h) * D + t2 * 4];
        float* d1 = &g_G[(1 * H + h) * D + t2 * 4];
        atomicAdd(d0 + 0, a0x); atomicAdd(d0 + 1, a0y); atomicAdd(d0 + 2, a0z); atomicAdd(d0 + 3, a0w);
        atomicAdd(d1 + 0, a1x); atomicAdd(d1 + 1, a1y); atomicAdd(d1 + 2, a1z); atomicAdd(d1 + 3, a1w);
    } else if (b == 64) {
        // bias = Wcmod.bv + Wc.bo + bc
        float s0 = 0.f, s1 = 0.f;
        if (tid < 256) {
            float4 m0 = make_float4(0.f, 0.f, 0.f, 0.f);
            float4 m1 = make_float4(0.f, 0.f, 0.f, 0.f);
            #pragma unroll 4
            for (int p = 0; p < 64; p++) {
                float4 v0 = reinterpret_cast<const float4*>(&g_wcp[(p * 2 + 0) * D])[tid];
                float4 v1 = reinterpret_cast<const float4*>(&g_wcp[(p * 2 + 1) * D])[tid];
                m0.x += v0.x; m0.y += v0.y; m0.z += v0.z; m0.w += v0.w;
                m1.x += v1.x; m1.y += v1.y; m1.z += v1.z; m1.w += v1.w;
            }
            float4 bvv = reinterpret_cast<const float4*>(bv)[tid];
            float4 bov = reinterpret_cast<const float4*>(bo)[tid];
            float4 wc0 = reinterpret_cast<const float4*>(Wc)[tid];
            float4 wc1 = reinterpret_cast<const float4*>(Wc)[256 + tid];
            s0 = m0.x * bvv.x + m0.y * bvv.y + m0.z * bvv.z + m0.w * bvv.w
               + wc0.x * bov.x + wc0.y * bov.y + wc0.z * bov.z + wc0.w * bov.w;
            s1 = m1.x * bvv.x + m1.y * bvv.y + m1.z * bvv.z + m1.w * bvv.w
               + wc1.x * bov.x + wc1.y * bov.y + wc1.z * bov.z + wc1.w * bov.w;
        }
        su.d.red0[tid] = s0; su.d.red1[tid] = s1;
        __syncthreads();
        for (int o = 256; o; o >>= 1) {
            if (tid < o) { su.d.red0[tid] += su.d.red0[tid + o]; su.d.red1[tid] += su.d.red1[tid + o]; }
            __syncthreads();
        }
        if (tid == 0) { g_bias[0] = su.d.red0[0] + bc[0]; g_bias[1] = su.d.red1[0] + bc[1]; }
    }
    grid_barrier(0);

    // ================= Phase C: x sweep (blocks 0..128) =====================
    int base = b * 64;
    if (b < 129) {
        #pragma unroll
        for (int i = 0; i < 16; i++) su.us[tid + i * NTHR] = g_u[tid + i * NTHR];
        __syncthreads();

        int tbase = base + warp * 4;
        const float* ptr[4];
        #pragma unroll
        for (int tt = 0; tt < 4; tt++) {
            int s = tbase + tt;
            ptr[tt] = (s <= 0 || s >= T) ? cls : x + (size_t)(s - 1) * D;
        }
        float acc[32];
        #pragma unroll
        for (int i = 0; i < 32; i++) acc[i] = 0.f;
        for (int k = 0; k < 32; k++) {
            int j = k * 32 + lane;
            float uv[8];
            #pragma unroll
            for (int h = 0; h < 8; h++) uv[h] = su.us[h * D + j];
            #pragma unroll
            for (int tt = 0; tt < 4; tt++) {
                float xv = ptr[tt][j];
                #pragma unroll
                for (int h = 0; h < 8; h++) acc[tt * 8 + h] += xv * uv[h];
            }
        }
        #pragma unroll
        for (int o = 16; o; o >>= 1) {
            #pragma unroll
            for (int i = 0; i < 32; i++) acc[i] += __shfl_xor_sync(0xffffffffu, acc[i], o);
        }
        {
            int tt = lane >> 3, h = lane & 7;      // lane r owns acc[r]
            int s = tbase + tt;
            int slot = (warp * 4 + tt) * 8 + h;
            s_wt[slot] = (s < T) ? expf(acc[lane] * SCALE) : 0.f;
        }
        __syncthreads();

        if (warp < 8) {
            int h = warp;
            float ssum = 0.f;
            #pragma unroll
            for (int t = lane; t < 64; t += 32) ssum += s_wt[t * 8 + h];
            #pragma unroll
            for (int o = 16; o; o >>= 1) ssum += __shfl_xor_sync(0xffffffffu, ssum, o);
            if (lane == 0) atomicAdd(&g_S[h], ssum);
        }

        float a[8][2];
        #pragma unroll
        for (int h = 0; h < 8; h++) { a[h][0] = 0.f; a[h][1] = 0.f; }
        for (int tt = 0; tt < 64; tt++) {
            int s = base + tt;
            if (s >= T) break;
            const float* p = (s == 0) ? cls : x + (size_t)(s - 1) * D;
            float2 xv = reinterpret_cast<const float2*>(p)[tid];
            #pragma unroll
            for (int h = 0; h < 8; h++) {
                float w = s_wt[tt * 8 + h];
                a[h][0] += w * xv.x; a[h][1] += w * xv.y;
            }
        }
        #pragma unroll
        for (int h = 0; h < 8; h++) {
            float* dst = &g_w[h * D + tid * 2];
            atomicAdd(dst + 0, a[h][0]); atomicAdd(dst + 1, a[h][1]);
        }
    }
    grid_barrier(1);

    // ================= Phase D: A (blocks 0..128) | logits (block 129) ======
    if (tid < H) s_rS[tid] = 1.f / g_S[tid];
    __syncthreads();

    if (b < 129) {
        if (tid < 64) {
            int s = base + tid;
            if (s >= 1 && s < T) {
                float a = 0.f;
                #pragma unroll
                for (int h = 0; h < 8; h++) a += s_wt[tid * 8 + h] * s_rS[h];
                out[6 + s] = a * 0.125f;           // A[s-1]
            }
        }
    } else if (b == 129) {
        float l0 = 0.f, l1 = 0.f;
        if (tid < 256) {
            #pragma unroll
            for (int h = 0; h < 8; h++) {
                float4 w4 = reinterpret_cast<const float4*>(&g_w[h * D])[tid];
                float4 g0 = reinterpret_cast<const float4*>(&g_G[(0 * H + h) * D])[tid];
                float4 g1 = reinterpret_cast<const float4*>(&g_G[(1 * H + h) * D])[tid];
                float r = s_rS[h];
                l0 += r * (g0.x * w4.x + g0.y * w4.y + g0.z * w4.z + g0.w * w4.w);
                l1 += r * (g1.x * w4.x + g1.y * w4.y + g1.z * w4.z + g1.w * w4.w);
            }
        }
        su.d.red0[tid] = l0; su.d.red1[tid] = l1;
        __syncthreads();
        for (int o = 256; o; o >>= 1) {
            if (tid < o) { su.d.red0[tid] += su.d.red0[tid + o]; su.d.red1[tid] += su.d.red1[tid + o]; }
            __syncthreads();
        }
        if (tid == 0) {
            float L0 = su.d.red0[0] + g_bias[0], L1 = su.d.red1[0] + g_bias[1];
            float mx = fmaxf(L0, L1);
            float e0 = expf(L0 - mx), e1 = expf(L1 - mx);
            float inv = 1.f / (e0 + e1);
            float p0 = e0 * inv, p1 = e1 * inv;
            float yhat = (p1 > p0) ? 1.f : 0.f;    // first-max tie-break like jnp.argmax
            out[0] = L0; out[1] = L1;              // top_instance
            out[2] = p0; out[3] = p1;              // Y_prob
            out[4] = yhat;                         // Y_hat
            out[5] = p0; out[6] = p1;              // y_probs
        }
    }
    grid_barrier(0);                               // even # barriers: sense ends at 0
}

extern "C" void kernel_launch(void* const* d_in, const int* in_sizes, int n_in,
                              void* d_out, int out_size) {
    const float* x   = (const float*)d_in[0];
    const float* cls = (const float*)d_in[1];
    const float* Wq  = (const float*)d_in[2];
    const float* bq  = (const float*)d_in[3];
    const float* Wk  = (const float*)d_in[4];
    // d_in[5] = bk: per-head constant shift of scores -> softmax-invariant, unused
    const float* Wv  = (const float*)d_in[6];
    const float* bv  = (const float*)d_in[7];
    const float* Wo  = (const float*)d_in[8];
    const float* bo  = (const float*)d_in[9];
    const float* Wc  = (const float*)d_in[10];
    const float* bc  = (const float*)d_in[11];
    float* out = (float*)d_out;

    Kfused<<<NBLK, NTHR>>>(x, cls, Wq, bq, Wk, Wv, bv, Wo, bo, Wc, bc, out);
    (void)in_sizes; (void)n_in; (void)out_size;
}